// round 14
// baseline (speedup 1.0000x reference)
#include <cuda_runtime.h>
#include <math.h>

#define NN 50000
#define NE 800000
#define NG 1024
#define IND 25
#define DIM 64
#define STEPS 3
#define SCAN_B 196                     // ceil(NN/256)
#define PLACE_B 782                    // ceil(NE/4/256)
#define LIN0_B 512

// ---------------- device scratch (statically allocated; no cudaMalloc) ------
// NOTE: g_deg is a pure in-edge COUNT (no self loop). It is zero at module
// load and k_scan resets it to zero after consuming it, so every replay of
// the captured graph sees zeros. Self loop is added arithmetically in k_scan.
__device__ float g_hw[NN * DIM];      // dinv[n] * (relu(x@W0+b0) @ Wc)   (pre-scaled!)
__device__ float g_h2[NN * DIM];      // relu(agg + bc)  -> set2set input
__device__ float g_dinv[NN];
__device__ int   g_deg[NN];           // in-edge count (zero before each pre)
__device__ int   g_rank[NE];          // edge rank within its target's list
__device__ int   g_coff[NN + 1];      // CSR offsets (in-edges, excl. self)
__device__ int   g_src[NE];           // CSR source list
__device__ int   g_goff[NG + 1];      // per-graph node ranges (batch sorted)
__device__ int   g_bsumf[SCAN_B];     // (block_sum << 1) | ready   (lookback)
// Transposed+packed gate weights: Q[k2*128 + j] =
//   { W(j,2k2), W(j+128,2k2), W(j,2k2+1), W(j+128,2k2+1) },
//   W(row,k) = Wih[row][k] + (k<64 ? Whh[row][k] : 0)
__device__ float4 g_Q[64 * 128];

// ------ pre: histogram(+rank), graph boundaries, flag clear, gate weights ---
__global__ void k_pre(const int* __restrict__ ei, const int* __restrict__ batch,
                      const float* __restrict__ Wih, const float* __restrict__ Whh) {
    int t = blockIdx.x * 256 + threadIdx.x;
    if (t < NE) {
        // returned old count == this edge's rank within target's in-edge list
        g_rank[t] = atomicAdd(&g_deg[ei[NE + t]], 1);
    }
    if (t < NN) {
        int bt = batch[t];
        if (t == 0) {
            for (int g = 0; g <= bt; g++) g_goff[g] = 0;
        } else {
            int bp = batch[t - 1];
            for (int g = bp + 1; g <= bt; g++) g_goff[g] = t;
        }
        if (t == NN - 1) {
            for (int g = bt + 1; g <= NG; g++) g_goff[g] = NN;
        }
    }
    if (t < SCAN_B) g_bsumf[t] = 0;                  // clear lookback flags
    if (t < 64 * 128) {                              // precombined gate weights
        int j = t & 127, k2 = t >> 7;
        int k0 = 2 * k2, k1 = k0 + 1;
        float4 q;
        q.x = Wih[j * 128 + k0]         + (k0 < 64 ? Whh[j * 64 + k0] : 0.f);
        q.y = Wih[(j + 128) * 128 + k0] + (k0 < 64 ? Whh[(j + 128) * 64 + k0] : 0.f);
        q.z = Wih[j * 128 + k1]         + (k1 < 64 ? Whh[j * 64 + k1] : 0.f);
        q.w = Wih[(j + 128) * 128 + k1] + (k1 < 64 ? Whh[(j + 128) * 64 + k1] : 0.f);
        g_Q[t] = q;
    }
    if (t == 0) g_coff[NN] = NE;      // sum(count) == NE identically
}

// ------ single-pass scan (decoupled lookback): coff = excl-scan(count) ------
// Consumes g_deg and resets it to 0 for the next replay.
__global__ void k_scan() {
    __shared__ int s[256];
    __shared__ int s_base;
    int tid = threadIdx.x;
    int b = blockIdx.x;
    int t = b * 256 + tid;
    int cnt = (t < NN) ? g_deg[t] : 0;
    if (t < NN) g_deg[t] = 0;                        // reset for next replay
    s[tid] = cnt;
    __syncthreads();
    #pragma unroll
    for (int off = 1; off < 256; off <<= 1) {
        int u = (tid >= off) ? s[tid - off] : 0;
        __syncthreads();
        s[tid] += u;
        __syncthreads();
    }
    // publish this block's aggregate (value and flag in one word -> no fence)
    if (tid == 0) atomicExch(&g_bsumf[b], (s[255] << 1) | 1);
    // warp 0: lookback over predecessors, 32 at a time
    if (tid < 32) {
        int base = 0;
        for (int j0 = b - 1; j0 >= 0; j0 -= 32) {
            int j = j0 - tid;
            int val = 0;
            if (j >= 0) {
                volatile int* p = g_bsumf + j;
                do { val = *p; } while (!(val & 1));
            }
            int contrib = (j >= 0) ? (val >> 1) : 0;
            #pragma unroll
            for (int o = 16; o > 0; o >>= 1)
                contrib += __shfl_xor_sync(0xffffffffu, contrib, o);
            base += contrib;
        }
        if (tid == 0) s_base = base;
    }
    __syncthreads();
    if (t < NN) {
        g_coff[t] = s_base + s[tid] - cnt;           // exclusive
        g_dinv[t] = rsqrtf((float)(cnt + 1));        // + self loop
    }
}

// ---- fused mid kernel: role-split grid = CSR placement || lin0 GEMM --------
// Blocks [0, PLACE_B): atomic-free placement (LSU-latency-bound).
// Blocks [PLACE_B, PLACE_B+LIN0_B): lin0(+relu)@Wc*dinv (FMA/LDS-bound).
// Complementary resources -> placement hides under the GEMM.
__global__ void __launch_bounds__(256) k_mid(
        const int* __restrict__ ei,
        const float* __restrict__ x, const float* __restrict__ W0,
        const float* __restrict__ b0, const float* __restrict__ Wc) {
    if (blockIdx.x < PLACE_B) {
        // ---------------- placement role ----------------
        int t = blockIdx.x * 256 + threadIdx.x;      // covers NE/4
        if (t >= NE / 4) return;
        int4 r4 = ((const int4*)ei)[t];
        int4 c4 = ((const int4*)(ei + NE))[t];
        int4 k4 = ((const int4*)g_rank)[t];
        g_src[g_coff[c4.x] + k4.x] = r4.x;
        g_src[g_coff[c4.y] + k4.y] = r4.y;
        g_src[g_coff[c4.z] + k4.z] = r4.z;
        g_src[g_coff[c4.w] + k4.w] = r4.w;
        return;
    }
    // ---------------- lin0 role ----------------
    __shared__ __align__(16) float sW0T[DIM][28];   // [d][k], zero-pad k>=25
    __shared__ __align__(16) float sWcT[DIM][68];   // [d][k], 4 pad words
    __shared__ float sb0[DIM];
    __shared__ __align__(16) float sx[16][28];      // [node][k], zero-padded
    __shared__ __align__(16) float sh[16][68];      // [node][k]
    __shared__ float sdin[16];
    int bid = blockIdx.x - PLACE_B;                  // 0..LIN0_B-1
    int tid = threadIdx.x;                           // 256 threads
    for (int i = tid; i < DIM * 28; i += 256) {
        int d = i / 28, k = i % 28;
        sW0T[d][k] = (k < IND) ? W0[k * DIM + d] : 0.f;
    }
    for (int i = tid; i < DIM * DIM; i += 256) {
        int k = i >> 6, d = i & 63;
        sWcT[d][k] = Wc[i];
    }
    if (tid < DIM) sb0[tid] = b0[tid];
    __syncthreads();
    int d = tid & 63, ng = tid >> 6;                 // ng in 0..3 -> 4 nodes
    int n0l = ng * 4;
    for (int base = bid * 16; base < NN; base += LIN0_B * 16) {
        for (int i = tid; i < 16 * 28; i += 256) {
            int nn = i / 28, k = i % 28;
            sx[nn][k] = (k < IND) ? x[(base + nn) * IND + k] : 0.f;
        }
        if (tid < 16) sdin[tid] = g_dinv[base + tid];
        __syncthreads();
        // ---- stage 1: h = relu(x@W0 + b0), 4 nodes per thread ----
        {
            float a0 = sb0[d], a1 = a0, a2 = a0, a3 = a0;
            const float4* w4 = (const float4*)sW0T[d];
            const float4* x0 = (const float4*)sx[n0l + 0];
            const float4* x1 = (const float4*)sx[n0l + 1];
            const float4* x2 = (const float4*)sx[n0l + 2];
            const float4* x3 = (const float4*)sx[n0l + 3];
            #pragma unroll
            for (int k4 = 0; k4 < 7; k4++) {
                float4 w = w4[k4];
                float4 v0 = x0[k4], v1 = x1[k4], v2 = x2[k4], v3 = x3[k4];
                a0 += w.x * v0.x + w.y * v0.y + w.z * v0.z + w.w * v0.w;
                a1 += w.x * v1.x + w.y * v1.y + w.z * v1.z + w.w * v1.w;
                a2 += w.x * v2.x + w.y * v2.y + w.z * v2.z + w.w * v2.w;
                a3 += w.x * v3.x + w.y * v3.y + w.z * v3.z + w.w * v3.w;
            }
            sh[n0l + 0][d] = fmaxf(a0, 0.f);
            sh[n0l + 1][d] = fmaxf(a1, 0.f);
            sh[n0l + 2][d] = fmaxf(a2, 0.f);
            sh[n0l + 3][d] = fmaxf(a3, 0.f);
        }
        __syncthreads();
        // ---- stage 2: hw = (h@Wc) * dinv ----
        {
            float c0 = 0.f, c1 = 0.f, c2 = 0.f, c3 = 0.f;
            const float4* u4 = (const float4*)sWcT[d];
            const float4* h0 = (const float4*)sh[n0l + 0];
            const float4* h1 = (const float4*)sh[n0l + 1];
            const float4* h2 = (const float4*)sh[n0l + 2];
            const float4* h3 = (const float4*)sh[n0l + 3];
            #pragma unroll
            for (int k4 = 0; k4 < 16; k4++) {
                float4 w = u4[k4];
                float4 v0 = h0[k4], v1 = h1[k4], v2 = h2[k4], v3 = h3[k4];
                c0 += w.x * v0.x + w.y * v0.y + w.z * v0.z + w.w * v0.w;
                c1 += w.x * v1.x + w.y * v1.y + w.z * v1.z + w.w * v1.w;
                c2 += w.x * v2.x + w.y * v2.y + w.z * v2.z + w.w * v2.w;
                c3 += w.x * v3.x + w.y * v3.y + w.z * v3.z + w.w * v3.w;
            }
            int n0 = base + n0l;
            g_hw[(n0 + 0) * DIM + d] = c0 * sdin[n0l + 0];
            g_hw[(n0 + 1) * DIM + d] = c1 * sdin[n0l + 1];
            g_hw[(n0 + 2) * DIM + d] = c2 * sdin[n0l + 2];
            g_hw[(n0 + 3) * DIM + d] = c3 * sdin[n0l + 3];
        }
        __syncthreads();
    }
}

// ------ gather (no atomics): h2 = relu(dn*(hw'[n] + sum hw'[src]) + bc) -----
__global__ void k_gather(const float* __restrict__ bc) {
    int warp_id = blockIdx.x * 8 + (threadIdx.x >> 5);
    int lane = threadIdx.x & 31;
    int half = lane >> 4, hl = lane & 15;
    int n = warp_id * 2 + half;
    if (n >= NN) return;
    unsigned hmask = half ? 0xffff0000u : 0x0000ffffu;
    const float4* hw4 = (const float4*)g_hw;
    float dn = g_dinv[n];
    float4 acc = hw4[n * 16 + hl];                   // self term (hw pre-scaled)
    int e0 = g_coff[n], e1 = g_coff[n + 1];
    for (int base = e0; base < e1; base += 16) {
        int m = min(16, e1 - base);
        int s = (hl < m) ? g_src[base + hl] : 0;
        int j = 0;
        for (; j + 4 <= m; j += 4) {
            int s0 = __shfl_sync(hmask, s, j,     16);
            int s1 = __shfl_sync(hmask, s, j + 1, 16);
            int s2 = __shfl_sync(hmask, s, j + 2, 16);
            int s3 = __shfl_sync(hmask, s, j + 3, 16);
            float4 v0 = hw4[s0 * 16 + hl];
            float4 v1 = hw4[s1 * 16 + hl];
            float4 v2 = hw4[s2 * 16 + hl];
            float4 v3 = hw4[s3 * 16 + hl];
            acc.x += (v0.x + v1.x) + (v2.x + v3.x);
            acc.y += (v0.y + v1.y) + (v2.y + v3.y);
            acc.z += (v0.z + v1.z) + (v2.z + v3.z);
            acc.w += (v0.w + v1.w) + (v2.w + v3.w);
        }
        for (; j < m; j++) {
            int sj = __shfl_sync(hmask, s, j, 16);
            float4 v = hw4[sj * 16 + hl];
            acc.x += v.x; acc.y += v.y; acc.z += v.z; acc.w += v.w;
        }
    }
    float4 b = ((const float4*)bc)[hl];
    float4 o;
    o.x = fmaxf(dn * acc.x + b.x, 0.f);
    o.y = fmaxf(dn * acc.y + b.y, 0.f);
    o.z = fmaxf(dn * acc.z + b.z, 0.f);
    o.w = fmaxf(dn * acc.w + b.w, 0.f);
    ((float4*)g_h2)[n * 16 + hl] = o;
}

// ------ fully fused Set2Set: 3 x (gates + LSTM cell + attention) + readout --
__global__ void k_s2s(const float* __restrict__ bih, const float* __restrict__ bhh,
                      const float* __restrict__ W1, const float* __restrict__ b1,
                      const float* __restrict__ W2, const float* __restrict__ b2,
                      float* __restrict__ out) {
    int g = blockIdx.x;
    int tid = threadIdx.x;
    int warp = tid >> 5, lane = tid & 31;
    __shared__ __align__(16) float s_hr[128];   // [h(64), r(64)]
    __shared__ __align__(16) float s_c[DIM];
    __shared__ float s_gate[256];
    __shared__ float sm[4], ssm[4];
    __shared__ float sr[4][DIM];
    __shared__ float red[DIM];

    int start = g_goff[g], end = g_goff[g + 1];
    float bsum0 = bih[tid] + bhh[tid];
    float bsum1 = bih[tid + 128] + bhh[tid + 128];
    s_hr[tid] = 0.f;
    if (tid < DIM) s_c[tid] = 0.f;
    __syncthreads();

    for (int step = 0; step < STEPS; step++) {
        // ---- gates: outputs tid and tid+128, coalesced weight reads ----
        float acc0 = bsum0, acc1 = bsum1;
        if (step > 0) {
            const float2* hr2 = (const float2*)s_hr;
            #pragma unroll 16
            for (int k2 = 0; k2 < 64; k2++) {
                float4 w = g_Q[k2 * 128 + tid];
                float2 hv = hr2[k2];
                acc0 += w.x * hv.x + w.z * hv.y;
                acc1 += w.y * hv.x + w.w * hv.y;
            }
        }
        s_gate[tid] = acc0;
        s_gate[tid + 128] = acc1;
        __syncthreads();
        // ---- LSTM cell ----
        if (tid < DIM) {
            float i = 1.f / (1.f + __expf(-s_gate[tid]));
            float f = 1.f / (1.f + __expf(-s_gate[64 + tid]));
            float gg = tanhf(s_gate[128 + tid]);
            float o = 1.f / (1.f + __expf(-s_gate[192 + tid]));
            float c = f * s_c[tid] + i * gg;
            s_c[tid] = c;
            s_hr[tid] = o * tanhf(c);               // h part
        }
        __syncthreads();
        // ---- attention: dual-stream online softmax over this graph's nodes --
        float q2x = s_hr[lane * 2], q2y = s_hr[lane * 2 + 1];
        float m0 = -1e30f, ws0 = 0.f, rx0 = 0.f, ry0 = 0.f;
        float m1 = -1e30f, ws1 = 0.f, rx1 = 0.f, ry1 = 0.f;
        for (int v = start + warp; v < end; v += 8) {
            int v2 = v + 4;
            bool has1 = (v2 < end);
            float2 hva = ((const float2*)g_h2)[v * 32 + lane];
            float2 hvb = has1 ? ((const float2*)g_h2)[v2 * 32 + lane]
                              : make_float2(0.f, 0.f);
            float da = hva.x * q2x + hva.y * q2y;
            float db = hvb.x * q2x + hvb.y * q2y;
            #pragma unroll
            for (int o = 16; o > 0; o >>= 1) {
                da += __shfl_xor_sync(0xffffffffu, da, o);
                db += __shfl_xor_sync(0xffffffffu, db, o);
            }
            {
                float nm = fmaxf(m0, da);
                float sc = __expf(m0 - nm);
                float w = __expf(da - nm);
                ws0 = ws0 * sc + w;
                rx0 = rx0 * sc + w * hva.x;
                ry0 = ry0 * sc + w * hva.y;
                m0 = nm;
            }
            if (has1) {
                float nm = fmaxf(m1, db);
                float sc = __expf(m1 - nm);
                float w = __expf(db - nm);
                ws1 = ws1 * sc + w;
                rx1 = rx1 * sc + w * hvb.x;
                ry1 = ry1 * sc + w * hvb.y;
                m1 = nm;
            }
        }
        // merge streams
        float m = fmaxf(m0, m1);
        float e0 = __expf(m0 - m), e1 = __expf(m1 - m);
        float wsum = ws0 * e0 + ws1 * e1;
        float rx = rx0 * e0 + rx1 * e1;
        float ry = ry0 * e0 + ry1 * e1;
        if (lane == 0) { sm[warp] = m; ssm[warp] = wsum; }
        sr[warp][lane * 2] = rx;
        sr[warp][lane * 2 + 1] = ry;
        __syncthreads();
        if (tid < DIM) {
            float M = fmaxf(fmaxf(sm[0], sm[1]), fmaxf(sm[2], sm[3]));
            float tot = 0.f, racc = 0.f;
            #pragma unroll
            for (int w = 0; w < 4; w++) {
                float e = __expf(sm[w] - M);
                tot += ssm[w] * e;
                racc += sr[w][tid] * e;
            }
            s_hr[64 + tid] = (end > start) ? racc / tot : 0.f;   // r part
        }
        __syncthreads();
    }
    // ---- readout: relu([h, r] @ W1 + b1) @ W2 + b2 ----
    if (tid < DIM) {
        float acc = b1[tid];
        #pragma unroll
        for (int k = 0; k < 128; k++) acc += s_hr[k] * W1[k * 64 + tid];
        acc = fmaxf(acc, 0.f) * W2[tid];
        #pragma unroll
        for (int o = 16; o > 0; o >>= 1) acc += __shfl_xor_sync(0xffffffffu, acc, o);
        if (lane == 0) red[warp] = acc;
    }
    __syncthreads();
    if (tid == 0) out[g] = red[0] + red[1] + b2[0];
}

// ---------------- launch sequence (5 launches) -------------------------------
extern "C" void kernel_launch(void* const* d_in, const int* in_sizes, int n_in,
                              void* d_out, int out_size) {
    const float* x     = (const float*)d_in[0];
    const int*   ei    = (const int*)  d_in[1];
    const int*   batch = (const int*)  d_in[2];
    const float* W0    = (const float*)d_in[3];
    const float* b0    = (const float*)d_in[4];
    const float* Wc    = (const float*)d_in[5];
    const float* bc    = (const float*)d_in[6];
    const float* Wih   = (const float*)d_in[7];
    const float* Whh   = (const float*)d_in[8];
    const float* bih   = (const float*)d_in[9];
    const float* bhh   = (const float*)d_in[10];
    const float* W1    = (const float*)d_in[11];
    const float* b1    = (const float*)d_in[12];
    const float* W2    = (const float*)d_in[13];
    const float* b2    = (const float*)d_in[14];
    float* out = (float*)d_out;

    k_pre<<<(NE + 255) / 256, 256>>>(ei, batch, Wih, Whh);
    k_scan<<<SCAN_B, 256>>>();
    k_mid<<<PLACE_B + LIN0_B, 256>>>(ei, x, W0, b0, Wc);
    k_gather<<<(NN / 2 + 7) / 8, 256>>>(bc);
    k_s2s<<<NG, 128>>>(bih, bhh, W1, b1, W2, b2, out);
}

// round 15
// speedup vs baseline: 1.0588x; 1.0588x over previous
#include <cuda_runtime.h>
#include <math.h>

#define NN 50000
#define NE 800000
#define NG 1024
#define IND 25
#define DIM 64
#define STEPS 3
#define SCAN_B 196                     // ceil(NN/256)

// ---------------- device scratch (statically allocated; no cudaMalloc) ------
// NOTE: g_deg is a pure in-edge COUNT (no self loop). It is zero at module
// load and k_scan resets it to zero after consuming it, so every replay of
// the captured graph sees zeros. Self loop is added arithmetically in k_scan.
__device__ float g_hw[NN * DIM];      // dinv[n] * (relu(x@W0+b0) @ Wc)   (pre-scaled!)
__device__ float g_h2[NN * DIM];      // relu(agg + bc)  -> set2set input
__device__ float g_dinv[NN];
__device__ int   g_deg[NN];           // in-edge count (zero before each pre)
__device__ int   g_rank[NE];          // edge rank within its target's list
__device__ int   g_coff[NN + 1];      // CSR offsets (in-edges, excl. self)
__device__ int   g_src[NE];           // CSR source list
__device__ int   g_goff[NG + 1];      // per-graph node ranges (batch sorted)
__device__ int   g_bsumf[SCAN_B];     // (block_sum << 1) | ready   (lookback)
// Transposed+packed gate weights: Q[k2*128 + j] =
//   { W(j,2k2), W(j+128,2k2), W(j,2k2+1), W(j+128,2k2+1) },
//   W(row,k) = Wih[row][k] + (k<64 ? Whh[row][k] : 0)
__device__ float4 g_Q[64 * 128];

// ------ pre: histogram(+rank), graph boundaries, flag clear, gate weights ---
__global__ void k_pre(const int* __restrict__ ei, const int* __restrict__ batch,
                      const float* __restrict__ Wih, const float* __restrict__ Whh) {
    int t = blockIdx.x * 256 + threadIdx.x;
    if (t < NE) {
        // returned old count == this edge's rank within target's in-edge list
        g_rank[t] = atomicAdd(&g_deg[ei[NE + t]], 1);
    }
    if (t < NN) {
        int bt = batch[t];
        if (t == 0) {
            for (int g = 0; g <= bt; g++) g_goff[g] = 0;
        } else {
            int bp = batch[t - 1];
            for (int g = bp + 1; g <= bt; g++) g_goff[g] = t;
        }
        if (t == NN - 1) {
            for (int g = bt + 1; g <= NG; g++) g_goff[g] = NN;
        }
    }
    if (t < SCAN_B) g_bsumf[t] = 0;                  // clear lookback flags
    if (t < 64 * 128) {                              // precombined gate weights
        int j = t & 127, k2 = t >> 7;
        int k0 = 2 * k2, k1 = k0 + 1;
        float4 q;
        q.x = Wih[j * 128 + k0]         + (k0 < 64 ? Whh[j * 64 + k0] : 0.f);
        q.y = Wih[(j + 128) * 128 + k0] + (k0 < 64 ? Whh[(j + 128) * 64 + k0] : 0.f);
        q.z = Wih[j * 128 + k1]         + (k1 < 64 ? Whh[j * 64 + k1] : 0.f);
        q.w = Wih[(j + 128) * 128 + k1] + (k1 < 64 ? Whh[(j + 128) * 64 + k1] : 0.f);
        g_Q[t] = q;
    }
    if (t == 0) g_coff[NN] = NE;      // sum(count) == NE identically
}

// ------ single-pass scan (decoupled lookback): coff = excl-scan(count) ------
// Consumes g_deg and resets it to 0 for the next replay.
__global__ void k_scan() {
    __shared__ int s[256];
    __shared__ int s_base;
    int tid = threadIdx.x;
    int b = blockIdx.x;
    int t = b * 256 + tid;
    int cnt = (t < NN) ? g_deg[t] : 0;
    if (t < NN) g_deg[t] = 0;                        // reset for next replay
    s[tid] = cnt;
    __syncthreads();
    #pragma unroll
    for (int off = 1; off < 256; off <<= 1) {
        int u = (tid >= off) ? s[tid - off] : 0;
        __syncthreads();
        s[tid] += u;
        __syncthreads();
    }
    // publish this block's aggregate (value and flag in one word -> no fence)
    if (tid == 0) atomicExch(&g_bsumf[b], (s[255] << 1) | 1);
    // warp 0: lookback over predecessors, 32 at a time
    if (tid < 32) {
        int base = 0;
        for (int j0 = b - 1; j0 >= 0; j0 -= 32) {
            int j = j0 - tid;
            int val = 0;
            if (j >= 0) {
                volatile int* p = g_bsumf + j;
                do { val = *p; } while (!(val & 1));
            }
            int contrib = (j >= 0) ? (val >> 1) : 0;
            #pragma unroll
            for (int o = 16; o > 0; o >>= 1)
                contrib += __shfl_xor_sync(0xffffffffu, contrib, o);
            base += contrib;
        }
        if (tid == 0) s_base = base;
    }
    __syncthreads();
    if (t < NN) {
        g_coff[t] = s_base + s[tid] - cnt;           // exclusive
        g_dinv[t] = rsqrtf((float)(cnt + 1));        // + self loop
    }
}

// ------ CSR placement: atomic-free (rank precomputed), int4-vectorized ------
__global__ void k_place(const int* __restrict__ ei) {
    int t = blockIdx.x * 256 + threadIdx.x;          // NE/4 = 200000 threads
    if (t >= NE / 4) return;
    int4 r4 = ((const int4*)ei)[t];
    int4 c4 = ((const int4*)(ei + NE))[t];
    int4 k4 = ((const int4*)g_rank)[t];
    g_src[g_coff[c4.x] + k4.x] = r4.x;
    g_src[g_coff[c4.y] + k4.y] = r4.y;
    g_src[g_coff[c4.z] + k4.z] = r4.z;
    g_src[g_coff[c4.w] + k4.w] = r4.w;
}

// ---- fused lin0(+relu), @Wc, dinv pre-scale; register-blocked, LDS.128 -----
__global__ void k_lin0(const float* __restrict__ x, const float* __restrict__ W0,
                       const float* __restrict__ b0, const float* __restrict__ Wc) {
    __shared__ __align__(16) float sW0T[DIM][28];   // [d][k], zero-pad k>=25
    __shared__ __align__(16) float sWcT[DIM][68];   // [d][k], 4 pad words
    __shared__ float sb0[DIM];
    __shared__ __align__(16) float sx[16][28];      // [node][k], zero-padded
    __shared__ __align__(16) float sh[16][68];      // [node][k]
    __shared__ float sdin[16];
    int tid = threadIdx.x;                           // 256 threads
    for (int i = tid; i < DIM * 28; i += 256) {
        int d = i / 28, k = i % 28;
        sW0T[d][k] = (k < IND) ? W0[k * DIM + d] : 0.f;
    }
    for (int i = tid; i < DIM * DIM; i += 256) {
        int k = i >> 6, d = i & 63;
        sWcT[d][k] = Wc[i];
    }
    if (tid < DIM) sb0[tid] = b0[tid];
    __syncthreads();
    int d = tid & 63, ng = tid >> 6;                 // ng in 0..3 -> 4 nodes
    int n0l = ng * 4;
    for (int base = blockIdx.x * 16; base < NN; base += gridDim.x * 16) {
        for (int i = tid; i < 16 * 28; i += 256) {
            int nn = i / 28, k = i % 28;
            sx[nn][k] = (k < IND) ? x[(base + nn) * IND + k] : 0.f;
        }
        if (tid < 16) sdin[tid] = g_dinv[base + tid];
        __syncthreads();
        // ---- stage 1: h = relu(x@W0 + b0), 4 nodes per thread ----
        {
            float a0 = sb0[d], a1 = a0, a2 = a0, a3 = a0;
            const float4* w4 = (const float4*)sW0T[d];
            const float4* x0 = (const float4*)sx[n0l + 0];
            const float4* x1 = (const float4*)sx[n0l + 1];
            const float4* x2 = (const float4*)sx[n0l + 2];
            const float4* x3 = (const float4*)sx[n0l + 3];
            #pragma unroll
            for (int k4 = 0; k4 < 7; k4++) {
                float4 w = w4[k4];
                float4 v0 = x0[k4], v1 = x1[k4], v2 = x2[k4], v3 = x3[k4];
                a0 += w.x * v0.x + w.y * v0.y + w.z * v0.z + w.w * v0.w;
                a1 += w.x * v1.x + w.y * v1.y + w.z * v1.z + w.w * v1.w;
                a2 += w.x * v2.x + w.y * v2.y + w.z * v2.z + w.w * v2.w;
                a3 += w.x * v3.x + w.y * v3.y + w.z * v3.z + w.w * v3.w;
            }
            sh[n0l + 0][d] = fmaxf(a0, 0.f);
            sh[n0l + 1][d] = fmaxf(a1, 0.f);
            sh[n0l + 2][d] = fmaxf(a2, 0.f);
            sh[n0l + 3][d] = fmaxf(a3, 0.f);
        }
        __syncthreads();
        // ---- stage 2: hw = (h@Wc) * dinv ----
        {
            float c0 = 0.f, c1 = 0.f, c2 = 0.f, c3 = 0.f;
            const float4* u4 = (const float4*)sWcT[d];
            const float4* h0 = (const float4*)sh[n0l + 0];
            const float4* h1 = (const float4*)sh[n0l + 1];
            const float4* h2 = (const float4*)sh[n0l + 2];
            const float4* h3 = (const float4*)sh[n0l + 3];
            #pragma unroll
            for (int k4 = 0; k4 < 16; k4++) {
                float4 w = u4[k4];
                float4 v0 = h0[k4], v1 = h1[k4], v2 = h2[k4], v3 = h3[k4];
                c0 += w.x * v0.x + w.y * v0.y + w.z * v0.z + w.w * v0.w;
                c1 += w.x * v1.x + w.y * v1.y + w.z * v1.z + w.w * v1.w;
                c2 += w.x * v2.x + w.y * v2.y + w.z * v2.z + w.w * v2.w;
                c3 += w.x * v3.x + w.y * v3.y + w.z * v3.z + w.w * v3.w;
            }
            int n0 = base + n0l;
            g_hw[(n0 + 0) * DIM + d] = c0 * sdin[n0l + 0];
            g_hw[(n0 + 1) * DIM + d] = c1 * sdin[n0l + 1];
            g_hw[(n0 + 2) * DIM + d] = c2 * sdin[n0l + 2];
            g_hw[(n0 + 3) * DIM + d] = c3 * sdin[n0l + 3];
        }
        __syncthreads();
    }
}

// ------ gather (no atomics): h2 = relu(dn*(hw'[n] + sum hw'[src]) + bc) -----
// 16 lanes per node (float4), 2 nodes per warp, 4-way unrolled neighbor loop.
__global__ void k_gather(const float* __restrict__ bc) {
    int warp_id = blockIdx.x * 8 + (threadIdx.x >> 5);
    int lane = threadIdx.x & 31;
    int half = lane >> 4, hl = lane & 15;
    int n = warp_id * 2 + half;
    if (n >= NN) return;
    unsigned hmask = half ? 0xffff0000u : 0x0000ffffu;
    const float4* hwp = ((const float4*)g_hw) + hl;  // hoisted lane base
    float dn = g_dinv[n];
    float4 acc = hwp[n * 16];                        // self term (hw pre-scaled)
    int e0 = g_coff[n], e1 = g_coff[n + 1];
    for (int base = e0; base < e1; base += 16) {
        int m = min(16, e1 - base);
        int s = (hl < m) ? g_src[base + hl] : 0;
        int j = 0;
        for (; j + 4 <= m; j += 4) {
            int s0 = __shfl_sync(hmask, s, j,     16);
            int s1 = __shfl_sync(hmask, s, j + 1, 16);
            int s2 = __shfl_sync(hmask, s, j + 2, 16);
            int s3 = __shfl_sync(hmask, s, j + 3, 16);
            float4 v0 = hwp[s0 * 16];
            float4 v1 = hwp[s1 * 16];
            float4 v2 = hwp[s2 * 16];
            float4 v3 = hwp[s3 * 16];
            acc.x += (v0.x + v1.x) + (v2.x + v3.x);
            acc.y += (v0.y + v1.y) + (v2.y + v3.y);
            acc.z += (v0.z + v1.z) + (v2.z + v3.z);
            acc.w += (v0.w + v1.w) + (v2.w + v3.w);
        }
        for (; j < m; j++) {
            int sj = __shfl_sync(hmask, s, j, 16);
            float4 v = hwp[sj * 16];
            acc.x += v.x; acc.y += v.y; acc.z += v.z; acc.w += v.w;
        }
    }
    float4 b = ((const float4*)bc)[hl];
    float4 o;
    o.x = fmaxf(dn * acc.x + b.x, 0.f);
    o.y = fmaxf(dn * acc.y + b.y, 0.f);
    o.z = fmaxf(dn * acc.z + b.z, 0.f);
    o.w = fmaxf(dn * acc.w + b.w, 0.f);
    ((float4*)g_h2)[n * 16 + hl] = o;
}

// ------ fully fused Set2Set: 3 x (gates + LSTM cell + attention) + readout --
__global__ void k_s2s(const float* __restrict__ bih, const float* __restrict__ bhh,
                      const float* __restrict__ W1, const float* __restrict__ b1,
                      const float* __restrict__ W2, const float* __restrict__ b2,
                      float* __restrict__ out) {
    int g = blockIdx.x;
    int tid = threadIdx.x;
    int warp = tid >> 5, lane = tid & 31;
    __shared__ __align__(16) float s_hr[128];   // [h(64), r(64)]
    __shared__ __align__(16) float s_c[DIM];
    __shared__ float s_gate[256];
    __shared__ float sm[4], ssm[4];
    __shared__ float sr[4][DIM];
    __shared__ float red[DIM];

    int start = g_goff[g], end = g_goff[g + 1];
    float bsum0 = bih[tid] + bhh[tid];
    float bsum1 = bih[tid + 128] + bhh[tid + 128];
    s_hr[tid] = 0.f;
    if (tid < DIM) s_c[tid] = 0.f;
    __syncthreads();

    for (int step = 0; step < STEPS; step++) {
        // ---- gates: outputs tid and tid+128, coalesced weight reads ----
        float acc0 = bsum0, acc1 = bsum1;
        if (step > 0) {
            const float2* hr2 = (const float2*)s_hr;
            #pragma unroll 16
            for (int k2 = 0; k2 < 64; k2++) {
                float4 w = g_Q[k2 * 128 + tid];
                float2 hv = hr2[k2];
                acc0 += w.x * hv.x + w.z * hv.y;
                acc1 += w.y * hv.x + w.w * hv.y;
            }
        }
        s_gate[tid] = acc0;
        s_gate[tid + 128] = acc1;
        __syncthreads();
        // ---- LSTM cell ----
        if (tid < DIM) {
            float i = 1.f / (1.f + __expf(-s_gate[tid]));
            float f = 1.f / (1.f + __expf(-s_gate[64 + tid]));
            float gg = tanhf(s_gate[128 + tid]);
            float o = 1.f / (1.f + __expf(-s_gate[192 + tid]));
            float c = f * s_c[tid] + i * gg;
            s_c[tid] = c;
            s_hr[tid] = o * tanhf(c);               // h part
        }
        __syncthreads();
        // ---- attention: dual-stream online softmax over this graph's nodes --
        float q2x = s_hr[lane * 2], q2y = s_hr[lane * 2 + 1];
        float m0 = -1e30f, ws0 = 0.f, rx0 = 0.f, ry0 = 0.f;
        float m1 = -1e30f, ws1 = 0.f, rx1 = 0.f, ry1 = 0.f;
        for (int v = start + warp; v < end; v += 8) {
            int v2 = v + 4;
            bool has1 = (v2 < end);
            float2 hva = ((const float2*)g_h2)[v * 32 + lane];
            float2 hvb = has1 ? ((const float2*)g_h2)[v2 * 32 + lane]
                              : make_float2(0.f, 0.f);
            float da = hva.x * q2x + hva.y * q2y;
            float db = hvb.x * q2x + hvb.y * q2y;
            #pragma unroll
            for (int o = 16; o > 0; o >>= 1) {
                da += __shfl_xor_sync(0xffffffffu, da, o);
                db += __shfl_xor_sync(0xffffffffu, db, o);
            }
            {
                float nm = fmaxf(m0, da);
                float sc = __expf(m0 - nm);
                float w = __expf(da - nm);
                ws0 = ws0 * sc + w;
                rx0 = rx0 * sc + w * hva.x;
                ry0 = ry0 * sc + w * hva.y;
                m0 = nm;
            }
            if (has1) {
                float nm = fmaxf(m1, db);
                float sc = __expf(m1 - nm);
                float w = __expf(db - nm);
                ws1 = ws1 * sc + w;
                rx1 = rx1 * sc + w * hvb.x;
                ry1 = ry1 * sc + w * hvb.y;
                m1 = nm;
            }
        }
        // merge streams
        float m = fmaxf(m0, m1);
        float e0 = __expf(m0 - m), e1 = __expf(m1 - m);
        float wsum = ws0 * e0 + ws1 * e1;
        float rx = rx0 * e0 + rx1 * e1;
        float ry = ry0 * e0 + ry1 * e1;
        if (lane == 0) { sm[warp] = m; ssm[warp] = wsum; }
        sr[warp][lane * 2] = rx;
        sr[warp][lane * 2 + 1] = ry;
        __syncthreads();
        if (tid < DIM) {
            float M = fmaxf(fmaxf(sm[0], sm[1]), fmaxf(sm[2], sm[3]));
            float tot = 0.f, racc = 0.f;
            #pragma unroll
            for (int w = 0; w < 4; w++) {
                float e = __expf(sm[w] - M);
                tot += ssm[w] * e;
                racc += sr[w][tid] * e;
            }
            s_hr[64 + tid] = (end > start) ? racc / tot : 0.f;   // r part
        }
        __syncthreads();
    }
    // ---- readout: relu([h, r] @ W1 + b1) @ W2 + b2 ----
    if (tid < DIM) {
        float acc = b1[tid];
        #pragma unroll
        for (int k = 0; k < 128; k++) acc += s_hr[k] * W1[k * 64 + tid];
        acc = fmaxf(acc, 0.f) * W2[tid];
        #pragma unroll
        for (int o = 16; o > 0; o >>= 1) acc += __shfl_xor_sync(0xffffffffu, acc, o);
        if (lane == 0) red[warp] = acc;
    }
    __syncthreads();
    if (tid == 0) out[g] = red[0] + red[1] + b2[0];
}

// ---------------- launch sequence (6 launches, strictly serial) -------------
extern "C" void kernel_launch(void* const* d_in, const int* in_sizes, int n_in,
                              void* d_out, int out_size) {
    const float* x     = (const float*)d_in[0];
    const int*   ei    = (const int*)  d_in[1];
    const int*   batch = (const int*)  d_in[2];
    const float* W0    = (const float*)d_in[3];
    const float* b0    = (const float*)d_in[4];
    const float* Wc    = (const float*)d_in[5];
    const float* bc    = (const float*)d_in[6];
    const float* Wih   = (const float*)d_in[7];
    const float* Whh   = (const float*)d_in[8];
    const float* bih   = (const float*)d_in[9];
    const float* bhh   = (const float*)d_in[10];
    const float* W1    = (const float*)d_in[11];
    const float* b1    = (const float*)d_in[12];
    const float* W2    = (const float*)d_in[13];
    const float* b2    = (const float*)d_in[14];
    float* out = (float*)d_out;

    k_pre<<<(NE + 255) / 256, 256>>>(ei, batch, Wih, Whh);
    k_scan<<<SCAN_B, 256>>>();
    k_place<<<(NE / 4 + 255) / 256, 256>>>(ei);
    k_lin0<<<512, 256>>>(x, W0, b0, Wc);
    k_gather<<<(NN / 2 + 7) / 8, 256>>>(bc);
    k_s2s<<<NG, 128>>>(bih, bhh, W1, b1, W2, b2, out);
}

// round 16
// speedup vs baseline: 1.0983x; 1.0373x over previous
#include <cuda_runtime.h>
#include <math.h>

#define NN 50000
#define NE 800000
#define NG 1024
#define IND 25
#define DIM 64
#define STEPS 3
#define SCAN_B 196                     // ceil(NN/256)

// ---------------- device scratch (statically allocated; no cudaMalloc) ------
// NOTE: g_deg is a pure in-edge COUNT (no self loop). It is zero at module
// load and k_scan resets it to zero after consuming it, so every replay of
// the captured graph sees zeros. Self loop is added arithmetically in k_scan.
__device__ float g_hw[NN * DIM];      // dinv[n] * (relu(x@W0+b0) @ Wc)   (pre-scaled!)
__device__ float g_h2[NN * DIM];      // relu(agg + bc)  -> set2set input
__device__ float g_dinv[NN];
__device__ int   g_deg[NN];           // in-edge count (zero before each pre)
__device__ int   g_rank[NE];          // edge rank within its target's list
__device__ int   g_coff[NN + 1];      // CSR offsets (in-edges, excl. self)
__device__ int   g_src[NE];           // CSR source list
__device__ int   g_goff[NG + 1];      // per-graph node ranges (batch sorted)
__device__ int   g_bsumf[SCAN_B];     // (block_sum << 1) | ready   (lookback)
// Transposed+packed gate weights: Q[k2*128 + j] =
//   { W(j,2k2), W(j+128,2k2), W(j,2k2+1), W(j+128,2k2+1) },
//   W(row,k) = Wih[row][k] + (k<64 ? Whh[row][k] : 0)
__device__ float4 g_Q[64 * 128];

// ------ pre: histogram(+rank), graph boundaries, flag clear, gate weights ---
__global__ void k_pre(const int* __restrict__ ei, const int* __restrict__ batch,
                      const float* __restrict__ Wih, const float* __restrict__ Whh) {
    int t = blockIdx.x * 256 + threadIdx.x;
    if (t < NE) {
        // returned old count == this edge's rank within target's in-edge list
        g_rank[t] = atomicAdd(&g_deg[ei[NE + t]], 1);
    }
    if (t < NN) {
        int bt = batch[t];
        if (t == 0) {
            for (int g = 0; g <= bt; g++) g_goff[g] = 0;
        } else {
            int bp = batch[t - 1];
            for (int g = bp + 1; g <= bt; g++) g_goff[g] = t;
        }
        if (t == NN - 1) {
            for (int g = bt + 1; g <= NG; g++) g_goff[g] = NN;
        }
    }
    if (t < SCAN_B) g_bsumf[t] = 0;                  // clear lookback flags
    if (t < 64 * 128) {                              // precombined gate weights
        int j = t & 127, k2 = t >> 7;
        int k0 = 2 * k2, k1 = k0 + 1;
        float4 q;
        q.x = Wih[j * 128 + k0]         + (k0 < 64 ? Whh[j * 64 + k0] : 0.f);
        q.y = Wih[(j + 128) * 128 + k0] + (k0 < 64 ? Whh[(j + 128) * 64 + k0] : 0.f);
        q.z = Wih[j * 128 + k1]         + (k1 < 64 ? Whh[j * 64 + k1] : 0.f);
        q.w = Wih[(j + 128) * 128 + k1] + (k1 < 64 ? Whh[(j + 128) * 64 + k1] : 0.f);
        g_Q[t] = q;
    }
    if (t == 0) g_coff[NN] = NE;      // sum(count) == NE identically
}

// ------ single-pass scan (decoupled lookback): coff = excl-scan(count) ------
// Consumes g_deg and resets it to 0 for the next replay.
__global__ void k_scan() {
    __shared__ int s[256];
    __shared__ int s_base;
    int tid = threadIdx.x;
    int b = blockIdx.x;
    int t = b * 256 + tid;
    int cnt = (t < NN) ? g_deg[t] : 0;
    if (t < NN) g_deg[t] = 0;                        // reset for next replay
    s[tid] = cnt;
    __syncthreads();
    #pragma unroll
    for (int off = 1; off < 256; off <<= 1) {
        int u = (tid >= off) ? s[tid - off] : 0;
        __syncthreads();
        s[tid] += u;
        __syncthreads();
    }
    // publish this block's aggregate (value and flag in one word -> no fence)
    if (tid == 0) atomicExch(&g_bsumf[b], (s[255] << 1) | 1);
    // warp 0: lookback over predecessors, 32 at a time
    if (tid < 32) {
        int base = 0;
        for (int j0 = b - 1; j0 >= 0; j0 -= 32) {
            int j = j0 - tid;
            int val = 0;
            if (j >= 0) {
                volatile int* p = g_bsumf + j;
                do { val = *p; } while (!(val & 1));
            }
            int contrib = (j >= 0) ? (val >> 1) : 0;
            #pragma unroll
            for (int o = 16; o > 0; o >>= 1)
                contrib += __shfl_xor_sync(0xffffffffu, contrib, o);
            base += contrib;
        }
        if (tid == 0) s_base = base;
    }
    __syncthreads();
    if (t < NN) {
        g_coff[t] = s_base + s[tid] - cnt;           // exclusive
        g_dinv[t] = rsqrtf((float)(cnt + 1));        // + self loop
    }
}

// ------ CSR placement: atomic-free (rank precomputed), int4-vectorized ------
__global__ void k_place(const int* __restrict__ ei) {
    int t = blockIdx.x * 256 + threadIdx.x;          // NE/4 = 200000 threads
    if (t >= NE / 4) return;
    int4 r4 = ((const int4*)ei)[t];
    int4 c4 = ((const int4*)(ei + NE))[t];
    int4 k4 = ((const int4*)g_rank)[t];
    g_src[g_coff[c4.x] + k4.x] = r4.x;
    g_src[g_coff[c4.y] + k4.y] = r4.y;
    g_src[g_coff[c4.z] + k4.z] = r4.z;
    g_src[g_coff[c4.w] + k4.w] = r4.w;
}

// ---- fused lin0(+relu), @Wc, dinv pre-scale; k-packed conflict-free LDS ----
// Weights stored k-packed: sWP[k4][d] = float4{ W[4k4..4k4+3][d] } so lanes
// (consecutive d) read 16B-consecutive shared addresses -> 4 wavefronts, no
// bank conflicts (the [d][k] row layout collided 8-way: stride 68 = 4 mod 32).
__global__ void k_lin0(const float* __restrict__ x, const float* __restrict__ W0,
                       const float* __restrict__ b0, const float* __restrict__ Wc) {
    __shared__ __align__(16) float4 sW0P[7][DIM];    // [k4][d], zero-pad k>=25
    __shared__ __align__(16) float4 sWcP[16][DIM];   // [k4][d]
    __shared__ float sb0[DIM];
    __shared__ __align__(16) float sx[16][28];       // [node][k], zero-padded
    __shared__ __align__(16) float sh[16][68];       // [node][k]
    __shared__ float sdin[16];
    int tid = threadIdx.x;                           // 256 threads
    for (int i = tid; i < 7 * DIM; i += 256) {
        int k4 = i >> 6, d = i & 63;
        float4 w;
        w.x = (4 * k4 + 0 < IND) ? W0[(4 * k4 + 0) * DIM + d] : 0.f;
        w.y = (4 * k4 + 1 < IND) ? W0[(4 * k4 + 1) * DIM + d] : 0.f;
        w.z = (4 * k4 + 2 < IND) ? W0[(4 * k4 + 2) * DIM + d] : 0.f;
        w.w = (4 * k4 + 3 < IND) ? W0[(4 * k4 + 3) * DIM + d] : 0.f;
        sW0P[k4][d] = w;
    }
    for (int i = tid; i < 16 * DIM; i += 256) {
        int k4 = i >> 6, d = i & 63;
        float4 w;
        w.x = Wc[(4 * k4 + 0) * DIM + d];
        w.y = Wc[(4 * k4 + 1) * DIM + d];
        w.z = Wc[(4 * k4 + 2) * DIM + d];
        w.w = Wc[(4 * k4 + 3) * DIM + d];
        sWcP[k4][d] = w;
    }
    if (tid < DIM) sb0[tid] = b0[tid];
    __syncthreads();
    int d = tid & 63, ng = tid >> 6;                 // ng in 0..3 -> 4 nodes
    int n0l = ng * 4;
    for (int base = blockIdx.x * 16; base < NN; base += gridDim.x * 16) {
        for (int i = tid; i < 16 * 28; i += 256) {
            int nn = i / 28, k = i % 28;
            sx[nn][k] = (k < IND) ? x[(base + nn) * IND + k] : 0.f;
        }
        if (tid < 16) sdin[tid] = g_dinv[base + tid];
        __syncthreads();
        // ---- stage 1: h = relu(x@W0 + b0), 4 nodes per thread ----
        {
            float a0 = sb0[d], a1 = a0, a2 = a0, a3 = a0;
            const float4* x0 = (const float4*)sx[n0l + 0];
            const float4* x1 = (const float4*)sx[n0l + 1];
            const float4* x2 = (const float4*)sx[n0l + 2];
            const float4* x3 = (const float4*)sx[n0l + 3];
            #pragma unroll
            for (int k4 = 0; k4 < 7; k4++) {
                float4 w = sW0P[k4][d];
                float4 v0 = x0[k4], v1 = x1[k4], v2 = x2[k4], v3 = x3[k4];
                a0 += w.x * v0.x + w.y * v0.y + w.z * v0.z + w.w * v0.w;
                a1 += w.x * v1.x + w.y * v1.y + w.z * v1.z + w.w * v1.w;
                a2 += w.x * v2.x + w.y * v2.y + w.z * v2.z + w.w * v2.w;
                a3 += w.x * v3.x + w.y * v3.y + w.z * v3.z + w.w * v3.w;
            }
            sh[n0l + 0][d] = fmaxf(a0, 0.f);
            sh[n0l + 1][d] = fmaxf(a1, 0.f);
            sh[n0l + 2][d] = fmaxf(a2, 0.f);
            sh[n0l + 3][d] = fmaxf(a3, 0.f);
        }
        __syncthreads();
        // ---- stage 2: hw = (h@Wc) * dinv ----
        {
            float c0 = 0.f, c1 = 0.f, c2 = 0.f, c3 = 0.f;
            const float4* h0 = (const float4*)sh[n0l + 0];
            const float4* h1 = (const float4*)sh[n0l + 1];
            const float4* h2 = (const float4*)sh[n0l + 2];
            const float4* h3 = (const float4*)sh[n0l + 3];
            #pragma unroll
            for (int k4 = 0; k4 < 16; k4++) {
                float4 w = sWcP[k4][d];
                float4 v0 = h0[k4], v1 = h1[k4], v2 = h2[k4], v3 = h3[k4];
                c0 += w.x * v0.x + w.y * v0.y + w.z * v0.z + w.w * v0.w;
                c1 += w.x * v1.x + w.y * v1.y + w.z * v1.z + w.w * v1.w;
                c2 += w.x * v2.x + w.y * v2.y + w.z * v2.z + w.w * v2.w;
                c3 += w.x * v3.x + w.y * v3.y + w.z * v3.z + w.w * v3.w;
            }
            int n0 = base + n0l;
            g_hw[(n0 + 0) * DIM + d] = c0 * sdin[n0l + 0];
            g_hw[(n0 + 1) * DIM + d] = c1 * sdin[n0l + 1];
            g_hw[(n0 + 2) * DIM + d] = c2 * sdin[n0l + 2];
            g_hw[(n0 + 3) * DIM + d] = c3 * sdin[n0l + 3];
        }
        __syncthreads();
    }
}

// ------ gather (no atomics): h2 = relu(dn*(hw'[n] + sum hw'[src]) + bc) -----
// 16 lanes per node (float4), 2 nodes per warp, 4-way unrolled neighbor loop.
__global__ void k_gather(const float* __restrict__ bc) {
    int warp_id = blockIdx.x * 8 + (threadIdx.x >> 5);
    int lane = threadIdx.x & 31;
    int half = lane >> 4, hl = lane & 15;
    int n = warp_id * 2 + half;
    if (n >= NN) return;
    unsigned hmask = half ? 0xffff0000u : 0x0000ffffu;
    const float4* hwp = ((const float4*)g_hw) + hl;  // hoisted lane base
    float dn = g_dinv[n];
    float4 acc = hwp[n * 16];                        // self term (hw pre-scaled)
    int e0 = g_coff[n], e1 = g_coff[n + 1];
    for (int base = e0; base < e1; base += 16) {
        int m = min(16, e1 - base);
        int s = (hl < m) ? g_src[base + hl] : 0;
        int j = 0;
        for (; j + 4 <= m; j += 4) {
            int s0 = __shfl_sync(hmask, s, j,     16);
            int s1 = __shfl_sync(hmask, s, j + 1, 16);
            int s2 = __shfl_sync(hmask, s, j + 2, 16);
            int s3 = __shfl_sync(hmask, s, j + 3, 16);
            float4 v0 = hwp[s0 * 16];
            float4 v1 = hwp[s1 * 16];
            float4 v2 = hwp[s2 * 16];
            float4 v3 = hwp[s3 * 16];
            acc.x += (v0.x + v1.x) + (v2.x + v3.x);
            acc.y += (v0.y + v1.y) + (v2.y + v3.y);
            acc.z += (v0.z + v1.z) + (v2.z + v3.z);
            acc.w += (v0.w + v1.w) + (v2.w + v3.w);
        }
        for (; j < m; j++) {
            int sj = __shfl_sync(hmask, s, j, 16);
            float4 v = hwp[sj * 16];
            acc.x += v.x; acc.y += v.y; acc.z += v.z; acc.w += v.w;
        }
    }
    float4 b = ((const float4*)bc)[hl];
    float4 o;
    o.x = fmaxf(dn * acc.x + b.x, 0.f);
    o.y = fmaxf(dn * acc.y + b.y, 0.f);
    o.z = fmaxf(dn * acc.z + b.z, 0.f);
    o.w = fmaxf(dn * acc.w + b.w, 0.f);
    ((float4*)g_h2)[n * 16 + hl] = o;
}

// ------ fully fused Set2Set: 3 x (gates + LSTM cell + attention) + readout --
__global__ void k_s2s(const float* __restrict__ bih, const float* __restrict__ bhh,
                      const float* __restrict__ W1, const float* __restrict__ b1,
                      const float* __restrict__ W2, const float* __restrict__ b2,
                      float* __restrict__ out) {
    int g = blockIdx.x;
    int tid = threadIdx.x;
    int warp = tid >> 5, lane = tid & 31;
    __shared__ __align__(16) float s_hr[128];   // [h(64), r(64)]
    __shared__ __align__(16) float s_c[DIM];
    __shared__ float s_gate[256];
    __shared__ float sm[4], ssm[4];
    __shared__ float sr[4][DIM];
    __shared__ float red[DIM];

    int start = g_goff[g], end = g_goff[g + 1];
    float bsum0 = bih[tid] + bhh[tid];
    float bsum1 = bih[tid + 128] + bhh[tid + 128];
    s_hr[tid] = 0.f;
    if (tid < DIM) s_c[tid] = 0.f;
    __syncthreads();

    for (int step = 0; step < STEPS; step++) {
        // ---- gates: outputs tid and tid+128, coalesced weight reads ----
        float acc0 = bsum0, acc1 = bsum1;
        if (step > 0) {
            const float2* hr2 = (const float2*)s_hr;
            #pragma unroll 16
            for (int k2 = 0; k2 < 64; k2++) {
                float4 w = g_Q[k2 * 128 + tid];
                float2 hv = hr2[k2];
                acc0 += w.x * hv.x + w.z * hv.y;
                acc1 += w.y * hv.x + w.w * hv.y;
            }
        }
        s_gate[tid] = acc0;
        s_gate[tid + 128] = acc1;
        __syncthreads();
        // ---- LSTM cell ----
        if (tid < DIM) {
            float i = 1.f / (1.f + __expf(-s_gate[tid]));
            float f = 1.f / (1.f + __expf(-s_gate[64 + tid]));
            float gg = tanhf(s_gate[128 + tid]);
            float o = 1.f / (1.f + __expf(-s_gate[192 + tid]));
            float c = f * s_c[tid] + i * gg;
            s_c[tid] = c;
            s_hr[tid] = o * tanhf(c);               // h part
        }
        __syncthreads();
        // ---- attention: dual-stream online softmax over this graph's nodes --
        float q2x = s_hr[lane * 2], q2y = s_hr[lane * 2 + 1];
        float m0 = -1e30f, ws0 = 0.f, rx0 = 0.f, ry0 = 0.f;
        float m1 = -1e30f, ws1 = 0.f, rx1 = 0.f, ry1 = 0.f;
        for (int v = start + warp; v < end; v += 8) {
            int v2 = v + 4;
            bool has1 = (v2 < end);
            float2 hva = ((const float2*)g_h2)[v * 32 + lane];
            float2 hvb = has1 ? ((const float2*)g_h2)[v2 * 32 + lane]
                              : make_float2(0.f, 0.f);
            float da = hva.x * q2x + hva.y * q2y;
            float db = hvb.x * q2x + hvb.y * q2y;
            #pragma unroll
            for (int o = 16; o > 0; o >>= 1) {
                da += __shfl_xor_sync(0xffffffffu, da, o);
                db += __shfl_xor_sync(0xffffffffu, db, o);
            }
            {
                float nm = fmaxf(m0, da);
                float sc = __expf(m0 - nm);
                float w = __expf(da - nm);
                ws0 = ws0 * sc + w;
                rx0 = rx0 * sc + w * hva.x;
                ry0 = ry0 * sc + w * hva.y;
                m0 = nm;
            }
            if (has1) {
                float nm = fmaxf(m1, db);
                float sc = __expf(m1 - nm);
                float w = __expf(db - nm);
                ws1 = ws1 * sc + w;
                rx1 = rx1 * sc + w * hvb.x;
                ry1 = ry1 * sc + w * hvb.y;
                m1 = nm;
            }
        }
        // merge streams
        float m = fmaxf(m0, m1);
        float e0 = __expf(m0 - m), e1 = __expf(m1 - m);
        float wsum = ws0 * e0 + ws1 * e1;
        float rx = rx0 * e0 + rx1 * e1;
        float ry = ry0 * e0 + ry1 * e1;
        if (lane == 0) { sm[warp] = m; ssm[warp] = wsum; }
        sr[warp][lane * 2] = rx;
        sr[warp][lane * 2 + 1] = ry;
        __syncthreads();
        if (tid < DIM) {
            float M = fmaxf(fmaxf(sm[0], sm[1]), fmaxf(sm[2], sm[3]));
            float tot = 0.f, racc = 0.f;
            #pragma unroll
            for (int w = 0; w < 4; w++) {
                float e = __expf(sm[w] - M);
                tot += ssm[w] * e;
                racc += sr[w][tid] * e;
            }
            s_hr[64 + tid] = (end > start) ? racc / tot : 0.f;   // r part
        }
        __syncthreads();
    }
    // ---- readout: relu([h, r] @ W1 + b1) @ W2 + b2 ----
    if (tid < DIM) {
        float acc = b1[tid];
        #pragma unroll
        for (int k = 0; k < 128; k++) acc += s_hr[k] * W1[k * 64 + tid];
        acc = fmaxf(acc, 0.f) * W2[tid];
        #pragma unroll
        for (int o = 16; o > 0; o >>= 1) acc += __shfl_xor_sync(0xffffffffu, acc, o);
        if (lane == 0) red[warp] = acc;
    }
    __syncthreads();
    if (tid == 0) out[g] = red[0] + red[1] + b2[0];
}

// ---------------- launch sequence (6 launches, strictly serial) -------------
extern "C" void kernel_launch(void* const* d_in, const int* in_sizes, int n_in,
                              void* d_out, int out_size) {
    const float* x     = (const float*)d_in[0];
    const int*   ei    = (const int*)  d_in[1];
    const int*   batch = (const int*)  d_in[2];
    const float* W0    = (const float*)d_in[3];
    const float* b0    = (const float*)d_in[4];
    const float* Wc    = (const float*)d_in[5];
    const float* bc    = (const float*)d_in[6];
    const float* Wih   = (const float*)d_in[7];
    const float* Whh   = (const float*)d_in[8];
    const float* bih   = (const float*)d_in[9];
    const float* bhh   = (const float*)d_in[10];
    const float* W1    = (const float*)d_in[11];
    const float* b1    = (const float*)d_in[12];
    const float* W2    = (const float*)d_in[13];
    const float* b2    = (const float*)d_in[14];
    float* out = (float*)d_out;

    k_pre<<<(NE + 255) / 256, 256>>>(ei, batch, Wih, Whh);
    k_scan<<<SCAN_B, 256>>>();
    k_place<<<(NE / 4 + 255) / 256, 256>>>(ei);
    k_lin0<<<512, 256>>>(x, W0, b0, Wc);
    k_gather<<<(NN / 2 + 7) / 8, 256>>>(bc);
    k_s2s<<<NG, 128>>>(bih, bhh, W1, b1, W2, b2, out);
}

// round 17
// speedup vs baseline: 1.1409x; 1.0388x over previous
#include <cuda_runtime.h>
#include <math.h>

#define NN 50000
#define NE 800000
#define NG 1024
#define IND 25
#define DIM 64
#define STEPS 3
#define SCAN_B 196                     // ceil(NN/256)

// ---------------- device scratch (statically allocated; no cudaMalloc) ------
// NOTE: g_deg is a pure in-edge COUNT (no self loop). It is zero at module
// load and k_scan resets it to zero after consuming it, so every replay of
// the captured graph sees zeros. Self loop is added arithmetically in k_scan.
__device__ float g_hw[NN * DIM];      // dinv[n] * (relu(x@W0+b0) @ Wc)   (pre-scaled!)
__device__ float g_h2[NN * DIM];      // relu(agg + bc)  -> set2set input
__device__ float g_dinv[NN];
__device__ int   g_deg[NN];           // in-edge count (zero before each pre)
__device__ int   g_rank[NE];          // edge rank within its target's list
__device__ int   g_coff[NN + 1];      // CSR offsets (in-edges, excl. self)
__device__ int   g_src[NE];           // CSR source list
__device__ int   g_goff[NG + 1];      // per-graph node ranges (batch sorted)
__device__ int   g_bsumf[SCAN_B];     // (block_sum << 1) | ready   (lookback)
// Transposed+packed gate weights: Q[k2*128 + j] =
//   { W(j,2k2), W(j+128,2k2), W(j,2k2+1), W(j+128,2k2+1) },
//   W(row,k) = Wih[row][k] + (k<64 ? Whh[row][k] : 0)
__device__ float4 g_Q[64 * 128];

// ------ pre: histogram(+rank), graph boundaries, flag clear, gate weights ---
__global__ void k_pre(const int* __restrict__ ei, const int* __restrict__ batch,
                      const float* __restrict__ Wih, const float* __restrict__ Whh) {
    int t = blockIdx.x * 256 + threadIdx.x;
    if (t < NE) {
        // returned old count == this edge's rank within target's in-edge list
        g_rank[t] = atomicAdd(&g_deg[ei[NE + t]], 1);
    }
    if (t < NN) {
        int bt = batch[t];
        if (t == 0) {
            for (int g = 0; g <= bt; g++) g_goff[g] = 0;
        } else {
            int bp = batch[t - 1];
            for (int g = bp + 1; g <= bt; g++) g_goff[g] = t;
        }
        if (t == NN - 1) {
            for (int g = bt + 1; g <= NG; g++) g_goff[g] = NN;
        }
    }
    if (t < SCAN_B) g_bsumf[t] = 0;                  // clear lookback flags
    if (t < 64 * 128) {                              // precombined gate weights
        int j = t & 127, k2 = t >> 7;
        int k0 = 2 * k2, k1 = k0 + 1;
        float4 q;
        q.x = Wih[j * 128 + k0]         + (k0 < 64 ? Whh[j * 64 + k0] : 0.f);
        q.y = Wih[(j + 128) * 128 + k0] + (k0 < 64 ? Whh[(j + 128) * 64 + k0] : 0.f);
        q.z = Wih[j * 128 + k1]         + (k1 < 64 ? Whh[j * 64 + k1] : 0.f);
        q.w = Wih[(j + 128) * 128 + k1] + (k1 < 64 ? Whh[(j + 128) * 64 + k1] : 0.f);
        g_Q[t] = q;
    }
    if (t == 0) g_coff[NN] = NE;      // sum(count) == NE identically
}

// ------ single-pass scan (decoupled lookback): coff = excl-scan(count) ------
// Consumes g_deg and resets it to 0 for the next replay.
__global__ void k_scan() {
    __shared__ int s[256];
    __shared__ int s_base;
    int tid = threadIdx.x;
    int b = blockIdx.x;
    int t = b * 256 + tid;
    int cnt = (t < NN) ? g_deg[t] : 0;
    if (t < NN) g_deg[t] = 0;                        // reset for next replay
    s[tid] = cnt;
    __syncthreads();
    #pragma unroll
    for (int off = 1; off < 256; off <<= 1) {
        int u = (tid >= off) ? s[tid - off] : 0;
        __syncthreads();
        s[tid] += u;
        __syncthreads();
    }
    // publish this block's aggregate (value and flag in one word -> no fence)
    if (tid == 0) atomicExch(&g_bsumf[b], (s[255] << 1) | 1);
    // warp 0: lookback over predecessors, 32 at a time
    if (tid < 32) {
        int base = 0;
        for (int j0 = b - 1; j0 >= 0; j0 -= 32) {
            int j = j0 - tid;
            int val = 0;
            if (j >= 0) {
                volatile int* p = g_bsumf + j;
                do { val = *p; } while (!(val & 1));
            }
            int contrib = (j >= 0) ? (val >> 1) : 0;
            #pragma unroll
            for (int o = 16; o > 0; o >>= 1)
                contrib += __shfl_xor_sync(0xffffffffu, contrib, o);
            base += contrib;
        }
        if (tid == 0) s_base = base;
    }
    __syncthreads();
    if (t < NN) {
        g_coff[t] = s_base + s[tid] - cnt;           // exclusive
        g_dinv[t] = rsqrtf((float)(cnt + 1));        // + self loop
    }
}

// ------ CSR placement: atomic-free (rank precomputed), int4-vectorized ------
__global__ void k_place(const int* __restrict__ ei) {
    int t = blockIdx.x * 256 + threadIdx.x;          // NE/4 = 200000 threads
    if (t >= NE / 4) return;
    int4 r4 = ((const int4*)ei)[t];
    int4 c4 = ((const int4*)(ei + NE))[t];
    int4 k4 = ((const int4*)g_rank)[t];
    g_src[g_coff[c4.x] + k4.x] = r4.x;
    g_src[g_coff[c4.y] + k4.y] = r4.y;
    g_src[g_coff[c4.z] + k4.z] = r4.z;
    g_src[g_coff[c4.w] + k4.w] = r4.w;
}

// ---- fused lin0(+relu), @Wc, dinv pre-scale; 8 nodes/thread, 32-node tiles -
// k-packed conflict-free weights. Per k4: 12 smem wavefronts vs 32 FMA-inst
// (16 FMA-pipe cycles) -> FMA-bound, crossbar no longer binds.
__global__ void k_lin0(const float* __restrict__ x, const float* __restrict__ W0,
                       const float* __restrict__ b0, const float* __restrict__ Wc) {
    __shared__ __align__(16) float4 sW0P[7][DIM];    // [k4][d], zero-pad k>=25
    __shared__ __align__(16) float4 sWcP[16][DIM];   // [k4][d]
    __shared__ float sb0[DIM];
    __shared__ __align__(16) float sx[32][28];       // [node][k], zero-padded
    __shared__ __align__(16) float sh[32][68];       // [node][k]
    __shared__ float sdin[32];
    int tid = threadIdx.x;                           // 256 threads
    for (int i = tid; i < 7 * DIM; i += 256) {
        int k4 = i >> 6, d = i & 63;
        float4 w;
        w.x = (4 * k4 + 0 < IND) ? W0[(4 * k4 + 0) * DIM + d] : 0.f;
        w.y = (4 * k4 + 1 < IND) ? W0[(4 * k4 + 1) * DIM + d] : 0.f;
        w.z = (4 * k4 + 2 < IND) ? W0[(4 * k4 + 2) * DIM + d] : 0.f;
        w.w = (4 * k4 + 3 < IND) ? W0[(4 * k4 + 3) * DIM + d] : 0.f;
        sW0P[k4][d] = w;
    }
    for (int i = tid; i < 16 * DIM; i += 256) {
        int k4 = i >> 6, d = i & 63;
        float4 w;
        w.x = Wc[(4 * k4 + 0) * DIM + d];
        w.y = Wc[(4 * k4 + 1) * DIM + d];
        w.z = Wc[(4 * k4 + 2) * DIM + d];
        w.w = Wc[(4 * k4 + 3) * DIM + d];
        sWcP[k4][d] = w;
    }
    if (tid < DIM) sb0[tid] = b0[tid];
    __syncthreads();
    int d = tid & 63, ng = tid >> 6;                 // ng in 0..3 -> 8 nodes
    int n0l = ng * 8;
    for (int base = blockIdx.x * 32; base < NN; base += gridDim.x * 32) {
        for (int i = tid; i < 32 * 28; i += 256) {
            int nn = i / 28, k = i % 28;
            int node = base + nn;
            sx[nn][k] = (k < IND && node < NN) ? x[node * IND + k] : 0.f;
        }
        if (tid < 32) sdin[tid] = (base + tid < NN) ? g_dinv[base + tid] : 0.f;
        __syncthreads();
        // ---- stage 1: h = relu(x@W0 + b0), 8 nodes per thread ----
        {
            float a[8];
            #pragma unroll
            for (int j = 0; j < 8; j++) a[j] = sb0[d];
            #pragma unroll
            for (int k4 = 0; k4 < 7; k4++) {
                float4 w = sW0P[k4][d];
                #pragma unroll
                for (int j = 0; j < 8; j++) {
                    float4 v = ((const float4*)sx[n0l + j])[k4];
                    a[j] += w.x * v.x + w.y * v.y + w.z * v.z + w.w * v.w;
                }
            }
            #pragma unroll
            for (int j = 0; j < 8; j++)
                sh[n0l + j][d] = fmaxf(a[j], 0.f);
        }
        __syncthreads();
        // ---- stage 2: hw = (h@Wc) * dinv ----
        {
            float c[8];
            #pragma unroll
            for (int j = 0; j < 8; j++) c[j] = 0.f;
            #pragma unroll
            for (int k4 = 0; k4 < 16; k4++) {
                float4 w = sWcP[k4][d];
                #pragma unroll
                for (int j = 0; j < 8; j++) {
                    float4 v = ((const float4*)sh[n0l + j])[k4];
                    c[j] += w.x * v.x + w.y * v.y + w.z * v.z + w.w * v.w;
                }
            }
            int n0 = base + n0l;
            #pragma unroll
            for (int j = 0; j < 8; j++) {
                if (n0 + j < NN)
                    g_hw[(n0 + j) * DIM + d] = c[j] * sdin[n0l + j];
            }
        }
        __syncthreads();
    }
}

// ------ gather (no atomics): h2 = relu(dn*(hw'[n] + sum hw'[src]) + bc) -----
// 16 lanes per node (float4), 2 nodes per warp, 4-way unrolled neighbor loop.
__global__ void k_gather(const float* __restrict__ bc) {
    int warp_id = blockIdx.x * 8 + (threadIdx.x >> 5);
    int lane = threadIdx.x & 31;
    int half = lane >> 4, hl = lane & 15;
    int n = warp_id * 2 + half;
    if (n >= NN) return;
    unsigned hmask = half ? 0xffff0000u : 0x0000ffffu;
    const float4* hwp = ((const float4*)g_hw) + hl;  // hoisted lane base
    float dn = g_dinv[n];
    float4 acc = hwp[n * 16];                        // self term (hw pre-scaled)
    int e0 = g_coff[n], e1 = g_coff[n + 1];
    for (int base = e0; base < e1; base += 16) {
        int m = min(16, e1 - base);
        int s = (hl < m) ? g_src[base + hl] : 0;
        int j = 0;
        for (; j + 4 <= m; j += 4) {
            int s0 = __shfl_sync(hmask, s, j,     16);
            int s1 = __shfl_sync(hmask, s, j + 1, 16);
            int s2 = __shfl_sync(hmask, s, j + 2, 16);
            int s3 = __shfl_sync(hmask, s, j + 3, 16);
            float4 v0 = hwp[s0 * 16];
            float4 v1 = hwp[s1 * 16];
            float4 v2 = hwp[s2 * 16];
            float4 v3 = hwp[s3 * 16];
            acc.x += (v0.x + v1.x) + (v2.x + v3.x);
            acc.y += (v0.y + v1.y) + (v2.y + v3.y);
            acc.z += (v0.z + v1.z) + (v2.z + v3.z);
            acc.w += (v0.w + v1.w) + (v2.w + v3.w);
        }
        for (; j < m; j++) {
            int sj = __shfl_sync(hmask, s, j, 16);
            float4 v = hwp[sj * 16];
            acc.x += v.x; acc.y += v.y; acc.z += v.z; acc.w += v.w;
        }
    }
    float4 b = ((const float4*)bc)[hl];
    float4 o;
    o.x = fmaxf(dn * acc.x + b.x, 0.f);
    o.y = fmaxf(dn * acc.y + b.y, 0.f);
    o.z = fmaxf(dn * acc.z + b.z, 0.f);
    o.w = fmaxf(dn * acc.w + b.w, 0.f);
    ((float4*)g_h2)[n * 16 + hl] = o;
}

// ------ fully fused Set2Set: 3 x (gates + LSTM cell + attention) + readout --
__global__ void k_s2s(const float* __restrict__ bih, const float* __restrict__ bhh,
                      const float* __restrict__ W1, const float* __restrict__ b1,
                      const float* __restrict__ W2, const float* __restrict__ b2,
                      float* __restrict__ out) {
    int g = blockIdx.x;
    int tid = threadIdx.x;
    int warp = tid >> 5, lane = tid & 31;
    __shared__ __align__(16) float s_hr[128];   // [h(64), r(64)]
    __shared__ __align__(16) float s_c[DIM];
    __shared__ float s_gate[256];
    __shared__ float sm[4], ssm[4];
    __shared__ float sr[4][DIM];
    __shared__ float red[DIM];

    int start = g_goff[g], end = g_goff[g + 1];
    float bsum0 = bih[tid] + bhh[tid];
    float bsum1 = bih[tid + 128] + bhh[tid + 128];
    s_hr[tid] = 0.f;
    if (tid < DIM) s_c[tid] = 0.f;
    __syncthreads();

    for (int step = 0; step < STEPS; step++) {
        // ---- gates: outputs tid and tid+128, coalesced weight reads ----
        float acc0 = bsum0, acc1 = bsum1;
        if (step > 0) {
            const float2* hr2 = (const float2*)s_hr;
            #pragma unroll 16
            for (int k2 = 0; k2 < 64; k2++) {
                float4 w = g_Q[k2 * 128 + tid];
                float2 hv = hr2[k2];
                acc0 += w.x * hv.x + w.z * hv.y;
                acc1 += w.y * hv.x + w.w * hv.y;
            }
        }
        s_gate[tid] = acc0;
        s_gate[tid + 128] = acc1;
        __syncthreads();
        // ---- LSTM cell ----
        if (tid < DIM) {
            float i = 1.f / (1.f + __expf(-s_gate[tid]));
            float f = 1.f / (1.f + __expf(-s_gate[64 + tid]));
            float gg = tanhf(s_gate[128 + tid]);
            float o = 1.f / (1.f + __expf(-s_gate[192 + tid]));
            float c = f * s_c[tid] + i * gg;
            s_c[tid] = c;
            s_hr[tid] = o * tanhf(c);               // h part
        }
        __syncthreads();
        // ---- attention: dual-stream online softmax over this graph's nodes --
        float q2x = s_hr[lane * 2], q2y = s_hr[lane * 2 + 1];
        float m0 = -1e30f, ws0 = 0.f, rx0 = 0.f, ry0 = 0.f;
        float m1 = -1e30f, ws1 = 0.f, rx1 = 0.f, ry1 = 0.f;
        for (int v = start + warp; v < end; v += 8) {
            int v2 = v + 4;
            bool has1 = (v2 < end);
            float2 hva = ((const float2*)g_h2)[v * 32 + lane];
            float2 hvb = has1 ? ((const float2*)g_h2)[v2 * 32 + lane]
                              : make_float2(0.f, 0.f);
            float da = hva.x * q2x + hva.y * q2y;
            float db = hvb.x * q2x + hvb.y * q2y;
            #pragma unroll
            for (int o = 16; o > 0; o >>= 1) {
                da += __shfl_xor_sync(0xffffffffu, da, o);
                db += __shfl_xor_sync(0xffffffffu, db, o);
            }
            {
                float nm = fmaxf(m0, da);
                float sc = __expf(m0 - nm);
                float w = __expf(da - nm);
                ws0 = ws0 * sc + w;
                rx0 = rx0 * sc + w * hva.x;
                ry0 = ry0 * sc + w * hva.y;
                m0 = nm;
            }
            if (has1) {
                float nm = fmaxf(m1, db);
                float sc = __expf(m1 - nm);
                float w = __expf(db - nm);
                ws1 = ws1 * sc + w;
                rx1 = rx1 * sc + w * hvb.x;
                ry1 = ry1 * sc + w * hvb.y;
                m1 = nm;
            }
        }
        // merge streams
        float m = fmaxf(m0, m1);
        float e0 = __expf(m0 - m), e1 = __expf(m1 - m);
        float wsum = ws0 * e0 + ws1 * e1;
        float rx = rx0 * e0 + rx1 * e1;
        float ry = ry0 * e0 + ry1 * e1;
        if (lane == 0) { sm[warp] = m; ssm[warp] = wsum; }
        sr[warp][lane * 2] = rx;
        sr[warp][lane * 2 + 1] = ry;
        __syncthreads();
        if (tid < DIM) {
            float M = fmaxf(fmaxf(sm[0], sm[1]), fmaxf(sm[2], sm[3]));
            float tot = 0.f, racc = 0.f;
            #pragma unroll
            for (int w = 0; w < 4; w++) {
                float e = __expf(sm[w] - M);
                tot += ssm[w] * e;
                racc += sr[w][tid] * e;
            }
            s_hr[64 + tid] = (end > start) ? racc / tot : 0.f;   // r part
        }
        __syncthreads();
    }
    // ---- readout: relu([h, r] @ W1 + b1) @ W2 + b2 ----
    if (tid < DIM) {
        float acc = b1[tid];
        #pragma unroll
        for (int k = 0; k < 128; k++) acc += s_hr[k] * W1[k * 64 + tid];
        acc = fmaxf(acc, 0.f) * W2[tid];
        #pragma unroll
        for (int o = 16; o > 0; o >>= 1) acc += __shfl_xor_sync(0xffffffffu, acc, o);
        if (lane == 0) red[warp] = acc;
    }
    __syncthreads();
    if (tid == 0) out[g] = red[0] + red[1] + b2[0];
}

// ---------------- launch sequence (6 launches, strictly serial) -------------
extern "C" void kernel_launch(void* const* d_in, const int* in_sizes, int n_in,
                              void* d_out, int out_size) {
    const float* x     = (const float*)d_in[0];
    const int*   ei    = (const int*)  d_in[1];
    const int*   batch = (const int*)  d_in[2];
    const float* W0    = (const float*)d_in[3];
    const float* b0    = (const float*)d_in[4];
    const float* Wc    = (const float*)d_in[5];
    const float* bc    = (const float*)d_in[6];
    const float* Wih   = (const float*)d_in[7];
    const float* Whh   = (const float*)d_in[8];
    const float* bih   = (const float*)d_in[9];
    const float* bhh   = (const float*)d_in[10];
    const float* W1    = (const float*)d_in[11];
    const float* b1    = (const float*)d_in[12];
    const float* W2    = (const float*)d_in[13];
    const float* b2    = (const float*)d_in[14];
    float* out = (float*)d_out;

    k_pre<<<(NE + 255) / 256, 256>>>(ei, batch, Wih, Whh);
    k_scan<<<SCAN_B, 256>>>();
    k_place<<<(NE / 4 + 255) / 256, 256>>>(ei);
    k_lin0<<<512, 256>>>(x, W0, b0, Wc);
    k_gather<<<(NN / 2 + 7) / 8, 256>>>(bc);
    k_s2s<<<NG, 128>>>(bih, bhh, W1, b1, W2, b2, out);
}